// round 10
// baseline (speedup 1.0000x reference)
#include <cuda_runtime.h>
#include <cuda_fp16.h>
#include <cstdint>

#define BATCH 8
#define NPTS  2048
#define CIN   64
#define NIP   256            // H width: [c(64) | e(192)]
#define MT    64             // a-rows per CTA
#define KC    64             // b's per chunk
#define NCHUNK (NPTS / KC)   // 32
#define THREADS 128          // 4 warps, warp tile 64x64

// Static device scratch (allocation is forbidden)
__device__ __align__(128) __half g_H[(size_t)BATCH * NIP * NPTS];  // [z][i'][b] fp16

// ---- main-kernel smem layout (bytes) ----
#define GEOM_OFF 0u                  // 2048 x float4 = 32768
#define A_OFF    32768u              // 2 x 8192 (64 rows x 128B, SW128)
#define A_STG    8192u
#define B_OFF    49152u              // 2 x 32768 (256 rows x 128B, SW128)
#define B_STG    32768u
#define SMEM_MAIN (B_OFF + 2u * B_STG)   // 114688 -> 2 CTAs/SM

// ---- prep-kernel smem (floats) ----
#define PWK_F   0
#define PE_F    12288                // E tile 192 x 72
#define PGB_F   26112                // 64 x float4
#define SMEM_PREP ((26112 + 256) * 4)

__device__ __forceinline__ uint32_t smem_u32(const void* p) {
    uint32_t a;
    asm("{ .reg .u64 t; cvta.to.shared.u64 t, %1; cvt.u32.u64 %0, t; }" : "=r"(a) : "l"(p));
    return a;
}
__device__ __forceinline__ void cpasync16(uint32_t dst, const void* src) {
    asm volatile("cp.async.cg.shared.global [%0], [%1], 16;" :: "r"(dst), "l"(src) : "memory");
}
__device__ __forceinline__ void sts32(uint32_t a, uint32_t v) {
    asm volatile("st.shared.b32 [%0], %1;" :: "r"(a), "r"(v) : "memory");
}
__device__ __forceinline__ void ldsm_x4(uint32_t& r0, uint32_t& r1, uint32_t& r2, uint32_t& r3,
                                        uint32_t addr) {
    asm volatile("ldmatrix.sync.aligned.m8n8.x4.shared.b16 {%0,%1,%2,%3}, [%4];"
                 : "=r"(r0), "=r"(r1), "=r"(r2), "=r"(r3) : "r"(addr));
}
__device__ __forceinline__ void mma16816(float& d0, float& d1, float& d2, float& d3,
                                         uint32_t a0, uint32_t a1, uint32_t a2, uint32_t a3,
                                         uint32_t b0, uint32_t b1) {
    asm volatile(
        "mma.sync.aligned.m16n8k16.row.col.f32.f16.f16.f32 "
        "{%0,%1,%2,%3}, {%4,%5,%6,%7}, {%8,%9}, {%0,%1,%2,%3};"
        : "+f"(d0), "+f"(d1), "+f"(d2), "+f"(d3)
        : "r"(a0), "r"(a1), "r"(a2), "r"(a3), "r"(b0), "r"(b1));
}

// ---------------------------------------------------------------------------
// Fused prep (unchanged from R9): per block (z, b-tile of 64):
//   E[192][64] in smem, then H rows (c for r<64, e shifted for r>=64),
//   written as fp16 straight to g_H [z][i'][b].
// ---------------------------------------------------------------------------
__global__ __launch_bounds__(256) void prep_kernel(const float* __restrict__ feat,
                                                   const float* __restrict__ geom,
                                                   const float* __restrict__ Wk) {
    extern __shared__ float sp[];
    float* s_wk = sp + PWK_F;
    float* s_E  = sp + PE_F;
    float4* s_gb = reinterpret_cast<float4*>(sp + PGB_F);

    const int z  = blockIdx.y;
    const int b0 = blockIdx.x * 64;
    const int t  = threadIdx.x;

    for (int m = t; m < 3 * 64 * 64 / 4; m += 256)
        reinterpret_cast<float4*>(s_wk)[m] = reinterpret_cast<const float4*>(Wk)[m];
    if (t < 64) {
        const float* gp = geom + ((size_t)z * NPTS + b0 + t) * 3;
        s_gb[t] = make_float4(gp[0], gp[1], gp[2], 0.0f);
    }

    const int bl = t & 63, q = t >> 6;
    float4 fr[16];
    const float4* fp = reinterpret_cast<const float4*>(
        feat + ((size_t)z * NPTS + b0 + bl) * CIN);
#pragma unroll
    for (int c = 0; c < 16; c++) fr[c] = fp[c];
    __syncthreads();

#pragma unroll 1
    for (int n = 0; n < 48; n++) {
        const int ii = q * 48 + n;
        const float4* w = reinterpret_cast<const float4*>(s_wk + ii * 64);
        float a0 = 0.f, a1 = 0.f, a2 = 0.f, a3 = 0.f;
#pragma unroll
        for (int c = 0; c < 16; c++) {
            const float4 wv = w[c];
            a0 = fmaf(fr[c].x, wv.x, a0);
            a1 = fmaf(fr[c].y, wv.y, a1);
            a2 = fmaf(fr[c].z, wv.z, a2);
            a3 = fmaf(fr[c].w, wv.w, a3);
        }
        s_E[ii * 72 + bl] = (a0 + a1) + (a2 + a3);
    }
    __syncthreads();

    const int wrp = t >> 5, l = t & 31;
    const float4 gbA = s_gb[2 * l];
    const float4 gbB = s_gb[2 * l + 1];
    uint32_t* Hh = reinterpret_cast<uint32_t*>(g_H);

#pragma unroll 1
    for (int rr = 0; rr < 32; rr++) {
        const int r = wrp * 32 + rr;
        float v0, v1;
        if (r < 64) {
            const float2 e0 = *reinterpret_cast<const float2*>(&s_E[r * 72 + 2 * l]);
            const float2 e1 = *reinterpret_cast<const float2*>(&s_E[(64 + r) * 72 + 2 * l]);
            const float2 e2 = *reinterpret_cast<const float2*>(&s_E[(128 + r) * 72 + 2 * l]);
            v0 = fmaf(gbA.x, e0.x, fmaf(gbA.y, e1.x, gbA.z * e2.x));
            v1 = fmaf(gbB.x, e0.y, fmaf(gbB.y, e1.y, gbB.z * e2.y));
        } else {
            const float2 e = *reinterpret_cast<const float2*>(&s_E[(r - 64) * 72 + 2 * l]);
            v0 = e.x; v1 = e.y;
        }
        const __half h0 = __float2half_rn(v0);
        const __half h1 = __float2half_rn(v1);
        const size_t idx = (((size_t)z * NIP + r) * NPTS + b0) / 2 + l;
        Hh[idx] = (uint32_t)__half_as_ushort(h0) | ((uint32_t)__half_as_ushort(h1) << 16);
    }
}

// issue one chunk's B copies (256 rows x 128B, SW128-swizzled), 128 threads
__device__ __forceinline__ void issue_b_copies(uint32_t bst, int z, int b0, int t) {
#pragma unroll
    for (int it = 0; it < 16; it++) {
        const int m = t + THREADS * it;          // 0..2047
        const int row = m >> 3, c16 = m & 7;
        const uint32_t dst = bst + (uint32_t)row * 128u
                           + (uint32_t)((c16 ^ (row & 7)) << 4);
        const __half* src = g_H + (((size_t)z * NIP + row) * NPTS + b0 + c16 * 8);
        cpasync16(dst, src);
    }
}

// ---------------------------------------------------------------------------
// Main: per CTA (z, 64 a-rows): P[64 x 256] = M @ H (fp16 HMMA, fp32 accum).
// 4 warps, warp tile 64x64 (pm=1, pn=4: minimal LDSM duplication),
// one syncthreads per chunk, double-buffered B, in-CTA mask tile A.
// ---------------------------------------------------------------------------
__global__ __launch_bounds__(THREADS, 2) void conv_mma_kernel(
    const float* __restrict__ geom, float* __restrict__ out)
{
    extern __shared__ __align__(16) char smem[];
    const uint32_t su = smem_u32(smem);
    float4* g4 = reinterpret_cast<float4*>(smem);

    const int z  = blockIdx.y;
    const int a0 = blockIdx.x * MT;
    const int t  = threadIdx.x;
    const int wid = t >> 5, lane = t & 31;
    const int n0 = wid * 64;                 // warp owns 64 output channels

    const float* gz = geom + (size_t)z * NPTS * 3;

    // prologue: chunk-0 B copies + stage whole-z geometry as float4
    issue_b_copies(su + B_OFF, z, 0, t);
    asm volatile("cp.async.commit_group;" ::: "memory");
    {
        float* gf = reinterpret_cast<float*>(smem);
        for (int idx = t; idx < NPTS * 3; idx += THREADS)
            gf[(idx / 3) * 4 + (idx % 3)] = gz[idx];
    }
    __syncthreads();

    // maskgen: thread t -> row rg (0..63), k-half sg (0/1)
    const int rg = t >> 1, sg = t & 1;
    const float4 ga = g4[a0 + rg];
    const uint32_t aw_base = su + A_OFF + (uint32_t)rg * 128u;
    const uint32_t rx = (uint32_t)(rg & 7);

    // ldsm lane bases
    const int rowA = ((lane >> 3) & 1) * 8 + (lane & 7);
    const uint32_t sA = (uint32_t)(lane >> 4), rxA = (uint32_t)(rowA & 7);
    const int rowB = n0 + ((lane >> 4) & 1) * 8 + (lane & 7);
    const uint32_t sB = (uint32_t)((lane >> 3) & 1), rxB = (uint32_t)(rowB & 7);

    float d[4][8][4];
#pragma unroll
    for (int mt = 0; mt < 4; mt++)
#pragma unroll
        for (int nt = 0; nt < 8; nt++)
#pragma unroll
            for (int r = 0; r < 4; r++) d[mt][nt][r] = 0.0f;

#pragma unroll 1
    for (int i = 0; i < NCHUNK; i++) {
        const uint32_t p = (uint32_t)(i & 1);
        const int b0 = i * KC;

        asm volatile("cp.async.wait_group 0;" ::: "memory");

        // ---- mask tile A[64 x 64] fp16 (SW128), diff-form norm test ----
        {
            const uint32_t ast = aw_base + p * A_STG;
#pragma unroll
            for (int v = 0; v < 16; v++) {
                const int veff = (v + rg) & 15;          // stagger reads
                const int k0 = sg * 32 + 2 * veff;
                const float4 q0 = g4[b0 + k0];
                const float4 q1 = g4[b0 + k0 + 1];
                const float dx0 = q0.x - ga.x, dy0 = q0.y - ga.y, dz0 = q0.z - ga.z;
                const float dx1 = q1.x - ga.x, dy1 = q1.y - ga.y, dz1 = q1.z - ga.z;
                const float nn0 = fmaf(dx0, dx0, fmaf(dy0, dy0, dz0 * dz0));
                const float nn1 = fmaf(dx1, dx1, fmaf(dy1, dy1, dz1 * dz1));
                const uint32_t val = (nn0 < 1.0f ? 0x3C00u : 0u)
                                   | (nn1 < 1.0f ? 0x3C000000u : 0u);
                const uint32_t bc = (uint32_t)(2 * k0);
                sts32(ast + (((bc >> 4) ^ rx) << 4) + (bc & 15u), val);
            }
        }
        __syncthreads();   // A(p)+B(p) visible; all warps done with stage p^1

        if (i + 1 < NCHUNK) {
            issue_b_copies(su + B_OFF + (p ^ 1u) * B_STG, z, b0 + KC, t);
            asm volatile("cp.async.commit_group;" ::: "memory");
        }

        // ---- ldmatrix + 128 HMMA per warp ----
        {
            const uint32_t Ast = su + A_OFF + p * A_STG;
            const uint32_t Bst = su + B_OFF + p * B_STG;
#pragma unroll
            for (int kk = 0; kk < 4; kk++) {
                uint32_t af[4][4];
#pragma unroll
                for (int mt = 0; mt < 4; mt++)
                    ldsm_x4(af[mt][0], af[mt][1], af[mt][2], af[mt][3],
                            Ast + (uint32_t)(rowA + mt * 16) * 128u
                                + ((((uint32_t)kk * 2u + sA) ^ rxA) << 4));
#pragma unroll
                for (int ntp = 0; ntp < 4; ntp++) {
                    uint32_t b0r, b1r, b2r, b3r;
                    ldsm_x4(b0r, b1r, b2r, b3r,
                            Bst + (uint32_t)(rowB + ntp * 16) * 128u
                               + ((((uint32_t)kk * 2u + sB) ^ rxB) << 4));
#pragma unroll
                    for (int mt = 0; mt < 4; mt++) {
                        mma16816(d[mt][2*ntp][0], d[mt][2*ntp][1], d[mt][2*ntp][2], d[mt][2*ntp][3],
                                 af[mt][0], af[mt][1], af[mt][2], af[mt][3], b0r, b1r);
                        mma16816(d[mt][2*ntp+1][0], d[mt][2*ntp+1][1], d[mt][2*ntp+1][2], d[mt][2*ntp+1][3],
                                 af[mt][0], af[mt][1], af[mt][2], af[mt][3], b2r, b3r);
                    }
                }
            }
        }
    }

    // ---- epilogue: P (overlays A/B region), combine, store ----
    __syncthreads();
    float* P = reinterpret_cast<float*>(smem + A_OFF);   // [64][260]
    const int fr = lane >> 2, fc = lane & 3;
#pragma unroll
    for (int mt = 0; mt < 4; mt++) {
#pragma unroll
        for (int nt = 0; nt < 8; nt++) {
            const int R0 = mt * 16 + fr;
            const int C  = n0 + nt * 8 + 2 * fc;
            *reinterpret_cast<float2*>(P + R0 * 260 + C)       = make_float2(d[mt][nt][0], d[mt][nt][1]);
            *reinterpret_cast<float2*>(P + (R0 + 8) * 260 + C) = make_float2(d[mt][nt][2], d[mt][nt][3]);
        }
    }
    __syncthreads();

    {
        const int al = t >> 1, iq = t & 1;
        const float4 ga4 = g4[a0 + al];
        float* orow = out + ((size_t)z * NPTS + a0 + al) * 64;
        const float* Pr = P + al * 260;
#pragma unroll
        for (int u = 0; u < 8; u++) {
            const int i0 = iq * 32 + u * 4;
            const float4 vc = *reinterpret_cast<const float4*>(Pr + i0);
            const float4 v1 = *reinterpret_cast<const float4*>(Pr + 64 + i0);
            const float4 v2 = *reinterpret_cast<const float4*>(Pr + 128 + i0);
            const float4 v3 = *reinterpret_cast<const float4*>(Pr + 192 + i0);
            float4 o;
            o.x = fmaf(-ga4.z, v3.x, fmaf(-ga4.y, v2.x, fmaf(-ga4.x, v1.x, vc.x)));
            o.y = fmaf(-ga4.z, v3.y, fmaf(-ga4.y, v2.y, fmaf(-ga4.x, v1.y, vc.y)));
            o.z = fmaf(-ga4.z, v3.z, fmaf(-ga4.y, v2.z, fmaf(-ga4.x, v1.z, vc.z)));
            o.w = fmaf(-ga4.z, v3.w, fmaf(-ga4.y, v2.w, fmaf(-ga4.x, v1.w, vc.w)));
            *reinterpret_cast<float4*>(orow + i0) = o;
        }
    }
}

// ---------------------------------------------------------------------------
// Launcher. Inputs: features [8,2048,64] f32, geometry [8,2048,3] f32,
// Wk [3,64,64] f32. Output [8,2048,64] f32.
// ---------------------------------------------------------------------------
extern "C" void kernel_launch(void* const* d_in, const int* in_sizes, int n_in,
                              void* d_out, int out_size) {
    const float* feat = (const float*)d_in[0];
    const float* geom = (const float*)d_in[1];
    const float* Wk   = (const float*)d_in[2];
    float* out = (float*)d_out;
    (void)in_sizes; (void)n_in; (void)out_size;

    cudaFuncSetAttribute(prep_kernel,
                         cudaFuncAttributeMaxDynamicSharedMemorySize, SMEM_PREP);
    cudaFuncSetAttribute(conv_mma_kernel,
                         cudaFuncAttributeMaxDynamicSharedMemorySize, SMEM_MAIN);

    prep_kernel<<<dim3(NPTS / 64, BATCH), 256, SMEM_PREP>>>(feat, geom, Wk);
    conv_mma_kernel<<<dim3(NPTS / MT, BATCH), THREADS, SMEM_MAIN>>>(geom, out);
}